// round 1
// baseline (speedup 1.0000x reference)
#include <cuda_runtime.h>
#include <math.h>

// Problem constants (fixed shapes)
#define TT 8192            // tokens = B*S
#define DD 1024            // model dim
#define EE 8               // experts
#define HH 3072            // hidden dim
#define PP (TT * 2)        // token-expert pairs (top-2)

// GEMM tiling
#define BM 128
#define BN 64
#define BK 16

// ---------------- scratch (device globals; no runtime alloc) ----------------
__device__ int   g_counts[EE];
__device__ int   g_cursor[EE];
__device__ int   g_offsets[EE + 1];
__device__ int   g_tok[PP];        // packed token index per pair
__device__ float g_wgt[PP];        // packed combine weight per pair
__device__ int   g_te[TT * 2];     // per-token top-2 expert ids
__device__ float g_tw[TT * 2];     // per-token top-2 weights
__device__ float g_h[(size_t)PP * HH];  // intermediate h (weight folded in)

// ---------------- init: zero output + routing counters ----------------
__global__ void k_init(float* __restrict__ out) {
    int i = blockIdx.x * blockDim.x + threadIdx.x;
    if (i < EE) { g_counts[i] = 0; g_cursor[i] = 0; }
    int stride = gridDim.x * blockDim.x;
    for (int j = i; j < TT * DD; j += stride) out[j] = 0.f;
}

// ---------------- gating: logits -> top2 -> renorm weights ----------------
__global__ void k_gate(const float* __restrict__ x, const float* __restrict__ gw) {
    int gid = blockIdx.x * blockDim.x + threadIdx.x;
    int t = gid >> 5, lane = gid & 31;
    if (t >= TT) return;
    const float* xr = x + (size_t)t * DD;
    float acc[EE];
#pragma unroll
    for (int e = 0; e < EE; e++) acc[e] = 0.f;
    for (int d = lane; d < DD; d += 32) {
        float xv = xr[d];
        const float4* g4 = (const float4*)(gw + (size_t)d * EE);
        float4 a = g4[0], b = g4[1];
        acc[0] += xv * a.x; acc[1] += xv * a.y; acc[2] += xv * a.z; acc[3] += xv * a.w;
        acc[4] += xv * b.x; acc[5] += xv * b.y; acc[6] += xv * b.z; acc[7] += xv * b.w;
    }
#pragma unroll
    for (int e = 0; e < EE; e++)
#pragma unroll
        for (int o = 16; o; o >>= 1) acc[e] += __shfl_xor_sync(0xffffffffu, acc[e], o);
    if (lane == 0) {
        int e0 = 0;
#pragma unroll
        for (int e = 1; e < EE; e++) if (acc[e] > acc[e0]) e0 = e;
        int e1 = (e0 == 0) ? 1 : 0;
#pragma unroll
        for (int e = 0; e < EE; e++) if (e != e0 && acc[e] > acc[e1]) e1 = e;
        // renormalized top-2 softmax weights == sigmoid(l0 - l1)
        float w0 = 1.f / (1.f + expf(acc[e1] - acc[e0]));
        g_te[2 * t] = e0; g_te[2 * t + 1] = e1;
        g_tw[2 * t] = w0; g_tw[2 * t + 1] = 1.f - w0;
        atomicAdd(&g_counts[e0], 1);
        atomicAdd(&g_counts[e1], 1);
    }
}

// ---------------- tiny exclusive scan over 8 experts ----------------
__global__ void k_scan() {
    int s = 0;
    g_offsets[0] = 0;
    for (int e = 0; e < EE; e++) { s += g_counts[e]; g_offsets[e + 1] = s; }
}

// ---------------- scatter tokens into per-expert packed lists ----------------
__global__ void k_scatter() {
    int t = blockIdx.x * blockDim.x + threadIdx.x;
    if (t >= TT) return;
#pragma unroll
    for (int k = 0; k < 2; k++) {
        int e = g_te[2 * t + k];
        int pos = g_offsets[e] + atomicAdd(&g_cursor[e], 1);
        g_tok[pos] = t;
        g_wgt[pos] = g_tw[2 * t + k];
    }
}

__device__ __forceinline__ float silu(float a) {
    return a / (1.f + expf(-a));
}

// ---------------- GEMM1: h = weight * silu(x@w1[e]) * (x@w3[e]) ----------------
// gathered rows; dual GEMM shares the x tile
__global__ void __launch_bounds__(256, 2) k_gemm1(
    const float* __restrict__ x,
    const float* __restrict__ w1,
    const float* __restrict__ w3) {
    int e = blockIdx.z;
    int segStart = g_offsets[e];
    int segLen = g_offsets[e + 1] - segStart;
    int row0 = blockIdx.x * BM;
    if (row0 >= segLen) return;
    int c0 = blockIdx.y * BN;

    __shared__ float sX[BM][BK];
    __shared__ float sW1[BK][BN];
    __shared__ float sW3[BK][BN];

    int tid = threadIdx.x;
    int tx = tid & 15, ty = tid >> 4;

    // X-tile loader assignment: each thread loads 2 rows x 4 cols
    int lr = tid >> 2;          // 0..63
    int lq = (tid & 3) * 4;     // k-quad within BK
    int tokA = -1, tokB = -1;
    if (row0 + lr < segLen)      tokA = g_tok[segStart + row0 + lr];
    if (row0 + lr + 64 < segLen) tokB = g_tok[segStart + row0 + lr + 64];

    // W-tile loader assignment: 16 rows x 64 cols, one float4 each
    int wr = tid >> 4;          // 0..15
    int wc = (tid & 15) * 4;

    const float* w1p = w1 + (size_t)e * DD * HH + c0;
    const float* w3p = w3 + (size_t)e * DD * HH + c0;

    float accA[8][4], accB[8][4];
#pragma unroll
    for (int i = 0; i < 8; i++)
#pragma unroll
        for (int j = 0; j < 4; j++) { accA[i][j] = 0.f; accB[i][j] = 0.f; }

    for (int k0 = 0; k0 < DD; k0 += BK) {
        float4 va = make_float4(0.f, 0.f, 0.f, 0.f), vb = va;
        if (tokA >= 0) va = *(const float4*)(x + (size_t)tokA * DD + k0 + lq);
        if (tokB >= 0) vb = *(const float4*)(x + (size_t)tokB * DD + k0 + lq);
        *(float4*)&sX[lr][lq] = va;
        *(float4*)&sX[lr + 64][lq] = vb;
        *(float4*)&sW1[wr][wc] = *(const float4*)(w1p + (size_t)(k0 + wr) * HH + wc);
        *(float4*)&sW3[wr][wc] = *(const float4*)(w3p + (size_t)(k0 + wr) * HH + wc);
        __syncthreads();
#pragma unroll
        for (int kk = 0; kk < BK; kk++) {
            float xr[8];
#pragma unroll
            for (int i = 0; i < 8; i++) xr[i] = sX[ty * 8 + i][kk];
            float4 a = *(float4*)&sW1[kk][tx * 4];
            float4 b = *(float4*)&sW3[kk][tx * 4];
#pragma unroll
            for (int i = 0; i < 8; i++) {
                accA[i][0] += xr[i] * a.x; accA[i][1] += xr[i] * a.y;
                accA[i][2] += xr[i] * a.z; accA[i][3] += xr[i] * a.w;
                accB[i][0] += xr[i] * b.x; accB[i][1] += xr[i] * b.y;
                accB[i][2] += xr[i] * b.z; accB[i][3] += xr[i] * b.w;
            }
        }
        __syncthreads();
    }

#pragma unroll
    for (int i = 0; i < 8; i++) {
        int r = row0 + ty * 8 + i;
        if (r < segLen) {
            float wgt = g_wgt[segStart + r];
            float4 hv;
            hv.x = wgt * accB[i][0] * silu(accA[i][0]);
            hv.y = wgt * accB[i][1] * silu(accA[i][1]);
            hv.z = wgt * accB[i][2] * silu(accA[i][2]);
            hv.w = wgt * accB[i][3] * silu(accA[i][3]);
            *(float4*)(g_h + (size_t)(segStart + r) * HH + c0 + tx * 4) = hv;
        }
    }
}

// ---------------- GEMM2: out[tok] += h_row @ w2[e] (weight already folded) ----------------
__global__ void __launch_bounds__(256, 2) k_gemm2(
    const float* __restrict__ w2, float* __restrict__ out) {
    int e = blockIdx.z;
    int segStart = g_offsets[e];
    int segLen = g_offsets[e + 1] - segStart;
    int row0 = blockIdx.x * BM;
    if (row0 >= segLen) return;
    int c0 = blockIdx.y * BN;

    __shared__ float sA[BM][BK];
    __shared__ float sB[BK][BN];

    int tid = threadIdx.x;
    int tx = tid & 15, ty = tid >> 4;

    int lr = tid >> 2;
    int lq = (tid & 3) * 4;
    bool okA = (row0 + lr) < segLen;
    bool okB = (row0 + lr + 64) < segLen;
    const float* hA = g_h + (size_t)(segStart + row0 + lr) * HH + lq;
    const float* hB = g_h + (size_t)(segStart + row0 + lr + 64) * HH + lq;

    int wr = tid >> 4;
    int wc = (tid & 15) * 4;
    const float* w2p = w2 + (size_t)e * HH * DD + c0;

    float acc[8][4];
#pragma unroll
    for (int i = 0; i < 8; i++)
#pragma unroll
        for (int j = 0; j < 4; j++) acc[i][j] = 0.f;

    for (int k0 = 0; k0 < HH; k0 += BK) {
        float4 va = make_float4(0.f, 0.f, 0.f, 0.f), vb = va;
        if (okA) va = *(const float4*)(hA + k0);
        if (okB) vb = *(const float4*)(hB + k0);
        *(float4*)&sA[lr][lq] = va;
        *(float4*)&sA[lr + 64][lq] = vb;
        *(float4*)&sB[wr][wc] = *(const float4*)(w2p + (size_t)(k0 + wr) * DD + wc);
        __syncthreads();
#pragma unroll
        for (int kk = 0; kk < BK; kk++) {
            float xr[8];
#pragma unroll
            for (int i = 0; i < 8; i++) xr[i] = sA[ty * 8 + i][kk];
            float4 b = *(float4*)&sB[kk][tx * 4];
#pragma unroll
            for (int i = 0; i < 8; i++) {
                acc[i][0] += xr[i] * b.x; acc[i][1] += xr[i] * b.y;
                acc[i][2] += xr[i] * b.z; acc[i][3] += xr[i] * b.w;
            }
        }
        __syncthreads();
    }

#pragma unroll
    for (int i = 0; i < 8; i++) {
        int r = row0 + ty * 8 + i;
        if (r < segLen) {
            int t = g_tok[segStart + r];
            float* op = out + (size_t)t * DD + c0 + tx * 4;
            atomicAdd(op + 0, acc[i][0]);
            atomicAdd(op + 1, acc[i][1]);
            atomicAdd(op + 2, acc[i][2]);
            atomicAdd(op + 3, acc[i][3]);
        }
    }
}

// ---------------- launch ----------------
extern "C" void kernel_launch(void* const* d_in, const int* in_sizes, int n_in,
                              void* d_out, int out_size) {
    // metadata order assumed = setup_inputs dict order: x, gate_w, w1, w3, w2
    const float* x  = (const float*)d_in[0];
    const float* gw = (const float*)d_in[1];
    const float* w1 = (const float*)d_in[2];
    const float* w3 = (const float*)d_in[3];
    const float* w2 = (const float*)d_in[4];
    float* out = (float*)d_out;

    k_init<<<4096, 256>>>(out);
    k_gate<<<TT / 8, 256>>>(x, gw);
    k_scan<<<1, 1>>>();
    k_scatter<<<TT / 256, 256>>>();
    k_gemm1<<<dim3(TT / BM, HH / BN, EE), 256>>>(x, w1, w3);
    k_gemm2<<<dim3(TT / BM, DD / BN, EE), 256>>>(w2, out);
}

// round 7
// speedup vs baseline: 3.4774x; 3.4774x over previous
#include <cuda_runtime.h>
#include <cuda_fp16.h>
#include <mma.h>
#include <math.h>
#include <stdint.h>

using namespace nvcuda;

// ---------------- problem constants ----------------
#define TT 8192
#define DD 1024
#define EE 8
#define HH 3072
#define PP (TT * 2)

// ---------------- scratch (device globals; ~101 MB total) ----------------
__device__ int    g_counts[EE];
__device__ int    g_cursor[EE];
__device__ int    g_offsets[EE + 1];
__device__ int    g_tok[PP];
__device__ float  g_wgt[PP];
__device__ int    g_te[TT * 2];
__device__ float  g_tw[TT * 2];
__device__ __half g_h[(size_t)PP * HH];   // fp16 SwiGLU intermediate (weight folded)

__device__ __forceinline__ float silu_f(float a) { return a / (1.f + __expf(-a)); }

// pack 8 fp32 -> 8 fp16 in a uint4
__device__ __forceinline__ uint4 f8h8(float4 a, float4 b) {
    __half2 h0 = __floats2half2_rn(a.x, a.y);
    __half2 h1 = __floats2half2_rn(a.z, a.w);
    __half2 h2 = __floats2half2_rn(b.x, b.y);
    __half2 h3 = __floats2half2_rn(b.z, b.w);
    uint4 u;
    u.x = *(uint32_t*)&h0; u.y = *(uint32_t*)&h1;
    u.z = *(uint32_t*)&h2; u.w = *(uint32_t*)&h3;
    return u;
}

// ---------------- init: zero output + routing counters (R1-proven) ----------------
__global__ void k_init(float* __restrict__ out) {
    int i = blockIdx.x * blockDim.x + threadIdx.x;
    if (i < EE) { g_counts[i] = 0; g_cursor[i] = 0; }
    int stride = gridDim.x * blockDim.x;
    for (int j = i; j < TT * DD; j += stride) out[j] = 0.f;
}

// ---------------- gating (R1-proven) ----------------
__global__ void k_gate(const float* __restrict__ x, const float* __restrict__ gw) {
    int gid = blockIdx.x * blockDim.x + threadIdx.x;
    int t = gid >> 5, lane = gid & 31;
    if (t >= TT) return;
    const float* xr = x + (size_t)t * DD;
    float acc[EE];
#pragma unroll
    for (int e = 0; e < EE; e++) acc[e] = 0.f;
    for (int d = lane; d < DD; d += 32) {
        float xv = xr[d];
        const float4* g4 = (const float4*)(gw + (size_t)d * EE);
        float4 a = g4[0], b = g4[1];
        acc[0] += xv * a.x; acc[1] += xv * a.y; acc[2] += xv * a.z; acc[3] += xv * a.w;
        acc[4] += xv * b.x; acc[5] += xv * b.y; acc[6] += xv * b.z; acc[7] += xv * b.w;
    }
#pragma unroll
    for (int e = 0; e < EE; e++)
#pragma unroll
        for (int o = 16; o; o >>= 1) acc[e] += __shfl_xor_sync(0xffffffffu, acc[e], o);
    if (lane == 0) {
        int e0 = 0;
#pragma unroll
        for (int e = 1; e < EE; e++) if (acc[e] > acc[e0]) e0 = e;
        int e1 = (e0 == 0) ? 1 : 0;
#pragma unroll
        for (int e = 0; e < EE; e++) if (e != e0 && acc[e] > acc[e1]) e1 = e;
        float w0 = 1.f / (1.f + expf(acc[e1] - acc[e0]));
        g_te[2 * t] = e0; g_te[2 * t + 1] = e1;
        g_tw[2 * t] = w0; g_tw[2 * t + 1] = 1.f - w0;
        atomicAdd(&g_counts[e0], 1);
        atomicAdd(&g_counts[e1], 1);
    }
}

__global__ void k_scan() {
    int s = 0;
    g_offsets[0] = 0;
    for (int e = 0; e < EE; e++) { s += g_counts[e]; g_offsets[e + 1] = s; }
}

__global__ void k_scatter() {
    int t = blockIdx.x * blockDim.x + threadIdx.x;
    if (t >= TT) return;
#pragma unroll
    for (int k = 0; k < 2; k++) {
        int e = g_te[2 * t + k];
        int pos = g_offsets[e] + atomicAdd(&g_cursor[e], 1);
        g_tok[pos] = t;
        g_wgt[pos] = g_tw[2 * t + k];
    }
}

// ============================================================================
// GEMM1: h = wgt * silu(x@w1) * (x@w3) — wmma 16x16x16, fp32 sources cvt on load
// Block: 128M x 64N x 32K; 8 warps = 4m x 2n, warp tile 32x32 (both operands)
// ============================================================================
__global__ void __launch_bounds__(256) k_gemm1(
    const float* __restrict__ x,
    const float* __restrict__ w1,
    const float* __restrict__ w3) {
    int e = blockIdx.z;
    int segStart = g_offsets[e];
    int segLen = g_offsets[e + 1] - segStart;
    int row0 = blockIdx.y * 128;
    if (row0 >= segLen) return;
    int n0 = blockIdx.x * 64;

    __shared__ __align__(16) __half sA[128 * 40];
    __shared__ __align__(16) __half sB1[32 * 72];
    __shared__ __align__(16) __half sB3[32 * 72];
    __shared__ __align__(16) float  scr[8 * 512];

    int tid = threadIdx.x, lane = tid & 31, wid = tid >> 5;
    int warp_m = wid & 3, warp_n = wid >> 2;

    // A loader: row = tid>>1, 16 fp32 at (tid&1)*16
    int ar = tid >> 1, ah = (tid & 1) * 16;
    int gr_a = row0 + ar;
    bool okA = gr_a < segLen;
    const float* aptr = x + (size_t)(okA ? g_tok[segStart + gr_a] : 0) * DD + ah;
    // B loaders: krow = tid>>3, 8 fp32 at (tid&7)*8
    int br = tid >> 3, bc = (tid & 7) * 8;
    const float* b1ptr = w1 + ((size_t)e * DD + br) * HH + n0 + bc;
    const float* b3ptr = w3 + ((size_t)e * DD + br) * HH + n0 + bc;

    wmma::fragment<wmma::accumulator, 16, 16, 16, float> acc1[2][2], acc3[2][2];
#pragma unroll
    for (int mt = 0; mt < 2; mt++)
#pragma unroll
        for (int nt = 0; nt < 2; nt++) {
            wmma::fill_fragment(acc1[mt][nt], 0.f);
            wmma::fill_fragment(acc3[mt][nt], 0.f);
        }

    const float4 FZ = make_float4(0.f, 0.f, 0.f, 0.f);
    uint4 ra0, ra1, rb1, rb3;
    {   // prologue: stage 0 to registers (fp32 load + cvt)
        const float4* p = (const float4*)aptr;
        ra0 = f8h8(okA ? p[0] : FZ, okA ? p[1] : FZ);
        ra1 = f8h8(okA ? p[2] : FZ, okA ? p[3] : FZ);
        const float4* q1 = (const float4*)b1ptr;
        rb1 = f8h8(q1[0], q1[1]);
        const float4* q3 = (const float4*)b3ptr;
        rb3 = f8h8(q3[0], q3[1]);
    }

    const int NS = DD / 32;
    for (int s = 0; s < NS; s++) {
        *(uint4*)(sA + ar * 40 + ah)     = ra0;
        *(uint4*)(sA + ar * 40 + ah + 8) = ra1;
        *(uint4*)(sB1 + br * 72 + bc)    = rb1;
        *(uint4*)(sB3 + br * 72 + bc)    = rb3;
        __syncthreads();
        if (s + 1 < NS) {
            const float4* p = (const float4*)(aptr + (s + 1) * 32);
            ra0 = f8h8(okA ? p[0] : FZ, okA ? p[1] : FZ);
            ra1 = f8h8(okA ? p[2] : FZ, okA ? p[3] : FZ);
            const float4* q1 = (const float4*)(b1ptr + (size_t)(s + 1) * 32 * HH);
            rb1 = f8h8(q1[0], q1[1]);
            const float4* q3 = (const float4*)(b3ptr + (size_t)(s + 1) * 32 * HH);
            rb3 = f8h8(q3[0], q3[1]);
        }
#pragma unroll
        for (int kt = 0; kt < 2; kt++) {
            wmma::fragment<wmma::matrix_a, 16, 16, 16, __half, wmma::row_major> af[2];
            wmma::load_matrix_sync(af[0], sA + (warp_m * 32) * 40 + kt * 16, 40);
            wmma::load_matrix_sync(af[1], sA + (warp_m * 32 + 16) * 40 + kt * 16, 40);
#pragma unroll
            for (int nt = 0; nt < 2; nt++) {
                wmma::fragment<wmma::matrix_b, 16, 16, 16, __half, wmma::row_major> bf;
                wmma::load_matrix_sync(bf, sB1 + (kt * 16) * 72 + warp_n * 32 + nt * 16, 72);
                wmma::mma_sync(acc1[0][nt], af[0], bf, acc1[0][nt]);
                wmma::mma_sync(acc1[1][nt], af[1], bf, acc1[1][nt]);
                wmma::load_matrix_sync(bf, sB3 + (kt * 16) * 72 + warp_n * 32 + nt * 16, 72);
                wmma::mma_sync(acc3[0][nt], af[0], bf, acc3[0][nt]);
                wmma::mma_sync(acc3[1][nt], af[1], bf, acc3[1][nt]);
            }
        }
        __syncthreads();
    }

    // epilogue: silu * gate * weight -> fp16 h
    float* w = scr + wid * 512;
    int r = lane >> 1, c = (lane & 1) * 8;
#pragma unroll
    for (int mt = 0; mt < 2; mt++) {
#pragma unroll
        for (int nt = 0; nt < 2; nt++) {
            wmma::store_matrix_sync(w, acc1[mt][nt], 16, wmma::mem_row_major);
            wmma::store_matrix_sync(w + 256, acc3[mt][nt], 16, wmma::mem_row_major);
            __syncwarp();
            int gr = row0 + warp_m * 32 + mt * 16 + r;
            if (gr < segLen) {
                float wgt = g_wgt[segStart + gr];
                __half* hp = g_h + (size_t)(segStart + gr) * HH + n0 + warp_n * 32 + nt * 16 + c;
#pragma unroll
                for (int j = 0; j < 8; j += 2) {
                    float f0 = wgt * silu_f(w[r * 16 + c + j])     * w[256 + r * 16 + c + j];
                    float f1 = wgt * silu_f(w[r * 16 + c + j + 1]) * w[256 + r * 16 + c + j + 1];
                    *(__half2*)(hp + j) = __floats2half2_rn(f0, f1);
                }
            }
            __syncwarp();
        }
    }
}

// ============================================================================
// GEMM2: out[tok] += h @ w2 — wmma, 128M x 128N x 32K; atomicAdd epilogue
// ============================================================================
__global__ void __launch_bounds__(256) k_gemm2(
    const float* __restrict__ w2, float* __restrict__ out) {
    int e = blockIdx.z;
    int segStart = g_offsets[e];
    int segLen = g_offsets[e + 1] - segStart;
    int row0 = blockIdx.y * 128;
    if (row0 >= segLen) return;
    int n0 = blockIdx.x * 128;

    __shared__ __align__(16) __half sA[128 * 40];
    __shared__ __align__(16) __half sB[32 * 136];
    __shared__ __align__(16) float  scr[8 * 256];

    int tid = threadIdx.x, lane = tid & 31, wid = tid >> 5;
    int warp_m = wid & 3, warp_n = wid >> 2;

    // A loader: fp16 h rows (16 halves/thread)
    int ar = tid >> 1, ah = (tid & 1) * 16;
    int gr_a = row0 + ar;
    bool okA = gr_a < segLen;
    const __half* aptr = g_h + (size_t)(segStart + (okA ? gr_a : 0)) * HH + ah;
    // B loader: w2 fp32, krow = tid>>3, 16 fp32 at (tid&7)*16
    int br = tid >> 3, bc = (tid & 7) * 16;
    const float* bptr = w2 + ((size_t)e * HH + br) * DD + n0 + bc;

    wmma::fragment<wmma::accumulator, 16, 16, 16, float> acc[2][4];
#pragma unroll
    for (int mt = 0; mt < 2; mt++)
#pragma unroll
        for (int nt = 0; nt < 4; nt++) wmma::fill_fragment(acc[mt][nt], 0.f);

    const uint4 Z = make_uint4(0, 0, 0, 0);
    uint4 ra0, ra1, rb0, rb1;
    {
        const uint4* p = (const uint4*)aptr;
        ra0 = okA ? p[0] : Z; ra1 = okA ? p[1] : Z;
        const float4* q = (const float4*)bptr;
        rb0 = f8h8(q[0], q[1]);
        rb1 = f8h8(q[2], q[3]);
    }

    const int NS = HH / 32;
    for (int s = 0; s < NS; s++) {
        *(uint4*)(sA + ar * 40 + ah)      = ra0;
        *(uint4*)(sA + ar * 40 + ah + 8)  = ra1;
        *(uint4*)(sB + br * 136 + bc)     = rb0;
        *(uint4*)(sB + br * 136 + bc + 8) = rb1;
        __syncthreads();
        if (s + 1 < NS) {
            const uint4* p = (const uint4*)(aptr + (s + 1) * 32);
            ra0 = okA ? p[0] : Z; ra1 = okA ? p[1] : Z;
            const float4* q = (const float4*)(bptr + (size_t)(s + 1) * 32 * DD);
            rb0 = f8h8(q[0], q[1]);
            rb1 = f8h8(q[2], q[3]);
        }
#pragma unroll
        for (int kt = 0; kt < 2; kt++) {
            wmma::fragment<wmma::matrix_a, 16, 16, 16, __half, wmma::row_major> af[2];
            wmma::load_matrix_sync(af[0], sA + (warp_m * 32) * 40 + kt * 16, 40);
            wmma::load_matrix_sync(af[1], sA + (warp_m * 32 + 16) * 40 + kt * 16, 40);
#pragma unroll
            for (int nt = 0; nt < 4; nt++) {
                wmma::fragment<wmma::matrix_b, 16, 16, 16, __half, wmma::row_major> bf;
                wmma::load_matrix_sync(bf, sB + (kt * 16) * 136 + warp_n * 64 + nt * 16, 136);
                wmma::mma_sync(acc[0][nt], af[0], bf, acc[0][nt]);
                wmma::mma_sync(acc[1][nt], af[1], bf, acc[1][nt]);
            }
        }
        __syncthreads();
    }

    // epilogue: atomicAdd into out (R1-proven combine; 2 adds/element total)
    float* w = scr + wid * 256;
    int r = lane >> 1, c = (lane & 1) * 8;
#pragma unroll
    for (int mt = 0; mt < 2; mt++) {
#pragma unroll
        for (int nt = 0; nt < 4; nt++) {
            wmma::store_matrix_sync(w, acc[mt][nt], 16, wmma::mem_row_major);
            __syncwarp();
            int gr = row0 + warp_m * 32 + mt * 16 + r;
            if (gr < segLen) {
                int tok = g_tok[segStart + gr];
                float* pp = out + (size_t)tok * DD + n0 + warp_n * 64 + nt * 16 + c;
#pragma unroll
                for (int j = 0; j < 8; j++) atomicAdd(pp + j, w[r * 16 + c + j]);
            }
            __syncwarp();
        }
    }
}

// ---------------- launch ----------------
extern "C" void kernel_launch(void* const* d_in, const int* in_sizes, int n_in,
                              void* d_out, int out_size) {
    const float* x  = (const float*)d_in[0];
    const float* gw = (const float*)d_in[1];
    const float* w1 = (const float*)d_in[2];
    const float* w3 = (const float*)d_in[3];
    const float* w2 = (const float*)d_in[4];
    float* out = (float*)d_out;

    k_init<<<4096, 256>>>(out);
    k_gate<<<TT / 8, 256>>>(x, gw);
    k_scan<<<1, 1>>>();
    k_scatter<<<TT / 256, 256>>>();
    k_gemm1<<<dim3(HH / 64, TT / 128, EE), 256>>>(x, w1, w3);
    k_gemm2<<<dim3(DD / 128, TT / 128, EE), 256>>>(w2, out);
}